// round 11
// baseline (speedup 1.0000x reference)
#include <cuda_runtime.h>
#include <cuda_bf16.h>
#include <cstdint>
#include <math.h>

#define B_  8
#define S_  2048
#define D_  512
#define NT_ 16          // psum slots per row (S_/128 column tiles)

// ---- GEMM tile config ----
#define BM 128
#define BN 128
#define KC 32           // K elements per chunk (64B of bf16 per row)
#define NCHUNK (D_/KC)  // 16
#define NSTAGE 3

// blocked gmem: one (128-row tile, 32-col chunk) = 128*64B = 8KB, swizzled
#define TILE_BYTES 8192

// stage layout (bytes): four 128x32 bf16 tiles
#define STG_A_HI 0
#define STG_A_LO 8192
#define STG_B_HI 16384
#define STG_B_LO 24576
#define STAGE_BYTES 32768
// 2048 slack: dynamic smem base is NOT 1024-aligned once static smem isn't a
// multiple of 1024; align-up may consume up to ~1KB (R9/R10 overflow bug).
#define SMEM_DYN (2048 + NSTAGE*STAGE_BYTES)   // 100352

// (1/sqrt(512)) * log2(e)
#define EXP2_SCALE 0.06376070918938434f

// ---------------- scratch (device globals; blocked/swizzled layouts) --------
__device__ __nv_bfloat16 g_xhi[B_*S_*D_];   // blocked: [(tile*16+chunk)*8192 + swz]
__device__ __nv_bfloat16 g_xlo[B_*S_*D_];
__device__ __nv_bfloat16 g_m2hi[D_*D_];     // blocked: 4 tiles x 16 chunks
__device__ __nv_bfloat16 g_m2lo[D_*D_];
__device__ __nv_bfloat16 g_uhi[B_*S_*D_];   // blocked (written by proj epilogue)
__device__ __nv_bfloat16 g_ulo[B_*S_*D_];
__device__ float         g_v2[D_];          // Wk @ bq
__device__ float         g_rk[B_*S_];       // (x[n].v2) * EXP2_SCALE
__device__ float         g_psum[B_*S_*NT_];
__device__ unsigned int  g_cnt[B_*NT_];     // per row-block arrival counters (atomicInc wraps)

// ---------------- helpers ----------------
__device__ __forceinline__ uint32_t smem_u32(const void* p) {
    uint32_t a;
    asm("{ .reg .u64 t; cvta.to.shared.u64 t, %1; cvt.u32.u64 %0, t; }" : "=r"(a) : "l"(p));
    return a;
}
__device__ __forceinline__ uint32_t swz64(uint32_t off) {
    return off ^ ((off >> 3) & 0x30);
}
__device__ __forceinline__ void mbar_init(uint32_t m, uint32_t cnt) {
    asm volatile("mbarrier.init.shared.b64 [%0], %1;" :: "r"(m), "r"(cnt) : "memory");
}
__device__ __forceinline__ void mbar_wait(uint32_t m, uint32_t parity) {
    asm volatile(
        "{\n\t.reg .pred P;\n\t"
        "W_%=:\n\t"
        "mbarrier.try_wait.parity.shared::cta.b64 P, [%0], %1, 10000000;\n\t"
        "@P bra.uni D_%=;\n\t"
        "bra.uni W_%=;\n\t"
        "D_%=:\n\t}"
        :: "r"(m), "r"(parity) : "memory");
}
__device__ __forceinline__ void mbar_arrive(uint32_t m) {
    asm volatile("mbarrier.arrive.shared.b64 _, [%0];" :: "r"(m) : "memory");
}
__device__ __forceinline__ void mbar_expect_tx(uint32_t m, uint32_t bytes) {
    asm volatile("mbarrier.arrive.expect_tx.shared.b64 _, [%0], %1;"
                 :: "r"(m), "r"(bytes) : "memory");
}
__device__ __forceinline__ void bulk_g2s(uint32_t dst, const void* src, uint32_t mbar) {
    asm volatile(
        "cp.async.bulk.shared::cluster.global.mbarrier::complete_tx::bytes [%0], [%1], %2, [%3];"
        :: "r"(dst), "l"(src), "r"((uint32_t)TILE_BYTES), "r"(mbar) : "memory");
}
__device__ __forceinline__ void ldsm_x4(uint32_t& r0, uint32_t& r1, uint32_t& r2, uint32_t& r3,
                                        uint32_t addr) {
    asm volatile("ldmatrix.sync.aligned.m8n8.x4.shared.b16 {%0,%1,%2,%3}, [%4];"
                 : "=r"(r0), "=r"(r1), "=r"(r2), "=r"(r3) : "r"(addr));
}
__device__ __forceinline__ void mma16816(float* c, const uint32_t* a, const uint32_t* b) {
    asm volatile(
        "mma.sync.aligned.m16n8k16.row.col.f32.bf16.bf16.f32 "
        "{%0,%1,%2,%3}, {%4,%5,%6,%7}, {%8,%9}, {%0,%1,%2,%3};"
        : "+f"(c[0]), "+f"(c[1]), "+f"(c[2]), "+f"(c[3])
        : "r"(a[0]), "r"(a[1]), "r"(a[2]), "r"(a[3]), "r"(b[0]), "r"(b[1]));
}

// blocked byte offset within a row-tile for (row in 0..127, col in 0..511)
__device__ __forceinline__ uint32_t blk_off(int r128, int col) {
    return (uint32_t)(col >> 5) * TILE_BYTES + swz64((uint32_t)(r128*64 + (col & 31)*2));
}

// ---------------- prep kernels ----------------
__global__ __launch_bounds__(256)
void v2_kernel(const float* __restrict__ Wk, const float* __restrict__ bq,
               float* __restrict__ v2)
{
    const int lane = threadIdx.x & 31;
    const int wrow = blockIdx.x * 8 + (threadIdx.x >> 5);
    float s = 0.0f;
    #pragma unroll
    for (int i = 0; i < 16; i++) {
        int d = i*32 + lane;
        s += Wk[(size_t)wrow*D_ + d] * bq[d];
    }
    #pragma unroll
    for (int o = 16; o > 0; o >>= 1) s += __shfl_xor_sync(0xffffffffu, s, o);
    if (lane == 0) v2[wrow] = s;
}

__global__ __launch_bounds__(256)
void split_x_rk_kernel(const float* __restrict__ in, const float* __restrict__ v2,
                       __nv_bfloat16* __restrict__ hi, __nv_bfloat16* __restrict__ lo,
                       float* __restrict__ rk)
{
    __shared__ float red[4][2];
    const int tid = threadIdx.x;
    const int rr  = tid >> 6;
    const int cg  = tid & 63;
    const int row = blockIdx.x * 4 + rr;
    const int col0 = cg * 8;

    const float* src = in + (size_t)row * D_ + col0;
    float4 v0 = *reinterpret_cast<const float4*>(src);
    float4 v1 = *reinterpret_cast<const float4*>(src + 4);
    float f[8] = {v0.x, v0.y, v0.z, v0.w, v1.x, v1.y, v1.z, v1.w};

    __nv_bfloat16 h[8], l[8];
    #pragma unroll
    for (int j = 0; j < 8; j++) {
        h[j] = __float2bfloat16(f[j]);
        l[j] = __float2bfloat16(f[j] - __bfloat162float(h[j]));
    }
    const size_t tbase = ((size_t)(row >> 7) * 16) * TILE_BYTES;
    const uint32_t off = blk_off(row & 127, col0);
    *reinterpret_cast<uint4*>((char*)hi + tbase + off) = *reinterpret_cast<uint4*>(h);
    *reinterpret_cast<uint4*>((char*)lo + tbase + off) = *reinterpret_cast<uint4*>(l);

    const float* w = v2 + col0;
    float local = 0.f;
    #pragma unroll
    for (int j = 0; j < 8; j++) local += f[j] * w[j];
    #pragma unroll
    for (int o = 16; o > 0; o >>= 1) local += __shfl_xor_sync(0xffffffffu, local, o);
    if ((tid & 31) == 0) red[rr][(cg >> 5)] = local;
    __syncthreads();
    if (cg == 0)
        rk[row] = (red[rr][0] + red[rr][1]) * EXP2_SCALE;
}

__global__ __launch_bounds__(256)
void m2t_kernel(const float* __restrict__ Wk, const float* __restrict__ Wq,
                __nv_bfloat16* __restrict__ m2hi, __nv_bfloat16* __restrict__ m2lo)
{
    __shared__ float sk[32][33];
    __shared__ float sq[32][33];
    const int tid = threadIdx.x;
    const int g0 = blockIdx.y * 32, f0 = blockIdx.x * 32;
    const int ty = tid >> 4, tx = tid & 15;

    float acc[2][2] = {{0.f,0.f},{0.f,0.f}};
    for (int d0 = 0; d0 < D_; d0 += 32) {
        #pragma unroll
        for (int p = 0; p < 4; p++) {
            int e = p*256 + tid;
            int r = e >> 5, c = e & 31;
            sk[r][c] = Wk[(size_t)(g0+r)*D_ + d0 + c];
            sq[r][c] = Wq[(size_t)(f0+r)*D_ + d0 + c];
        }
        __syncthreads();
        #pragma unroll
        for (int d = 0; d < 32; d++) {
            float k0v = sk[2*ty][d],   k1v = sk[2*ty+1][d];
            float q0v = sq[2*tx][d],   q1v = sq[2*tx+1][d];
            acc[0][0] = fmaf(k0v, q0v, acc[0][0]);
            acc[0][1] = fmaf(k0v, q1v, acc[0][1]);
            acc[1][0] = fmaf(k1v, q0v, acc[1][0]);
            acc[1][1] = fmaf(k1v, q1v, acc[1][1]);
        }
        __syncthreads();
    }
    #pragma unroll
    for (int i = 0; i < 2; i++)
        #pragma unroll
        for (int j = 0; j < 2; j++) {
            float v = acc[i][j];
            __nv_bfloat16 h = __float2bfloat16(v);
            __nv_bfloat16 l = __float2bfloat16(v - __bfloat162float(h));
            int g = g0 + 2*ty + i;
            int f = f0 + 2*tx + j;
            size_t tbase = ((size_t)(g >> 7) * 16) * TILE_BYTES;
            uint32_t off = blk_off(g & 127, f);
            *reinterpret_cast<__nv_bfloat16*>((char*)m2hi + tbase + off) = h;
            *reinterpret_cast<__nv_bfloat16*>((char*)m2lo + tbase + off) = l;
        }
}

// ---------------- NT GEMM with bulk producer + mbarrier rings ---------------
// MODE 0: u-projection -> out = A@B^T, stored bf16 hi/lo BLOCKED
// MODE 1: scores       -> out = exp2(scale*(A@B^T) + rk[n]) fp32 + row psums,
//                         then LAST-FINISHER normalizes the whole row block.
template<int MODE>
__global__ __launch_bounds__(256, 2)
void gemm_nt_kernel(const __nv_bfloat16* __restrict__ aHiBase,
                    const __nv_bfloat16* __restrict__ aLoBase,
                    const __nv_bfloat16* __restrict__ bHiBase,
                    const __nv_bfloat16* __restrict__ bLoBase,
                    const float* __restrict__ rk_s,
                    __nv_bfloat16* __restrict__ outHi,
                    __nv_bfloat16* __restrict__ outLo,
                    float* outF,
                    float* psum,
                    unsigned int* cnt)
{
    extern __shared__ char smem_raw[];
    const uint32_t sb = (smem_u32(smem_raw) + 1023u) & ~1023u;
    __shared__ float s_rowsum[128][4];
    __shared__ float s_inv[128];
    __shared__ int   s_last;

    const int tid    = threadIdx.x;
    const int lane   = tid & 31;
    const int wid    = tid >> 5;
    const int warp_m = wid & 1;      // 2 warps in M (64 rows each)
    const int warp_n = wid >> 1;     // 4 warps in N (32 cols each)

    int atile, btile, arow0, ncol0;
    if (MODE == 0) {
        atile = blockIdx.y;               // x tile
        btile = blockIdx.x;               // m2 tile (0..3)
        arow0 = atile * BM;
        ncol0 = btile * BN;
    } else {
        const int b = blockIdx.z;
        atile = b * 16 + blockIdx.y;      // u tile
        btile = b * 16 + blockIdx.x;      // x tile
        arow0 = atile * BM;
        ncol0 = blockIdx.x * BN;
    }
    const char* aHiB = (const char*)aHiBase + (size_t)atile * 16 * TILE_BYTES;
    const char* aLoB = (const char*)aLoBase + (size_t)atile * 16 * TILE_BYTES;
    const char* bHiB = (const char*)bHiBase + (size_t)btile * 16 * TILE_BYTES;
    const char* bLoB = (const char*)bLoBase + (size_t)btile * 16 * TILE_BYTES;
    const float* rkb = (MODE == 1) ? (rk_s + (size_t)blockIdx.z * S_) : rk_s;

    // mbarriers: full[s] at sb+s*8 (count 1+tx), empty[s] at sb+24+s*8 (count 8)
    if (tid == 0) {
        #pragma unroll
        for (int s = 0; s < NSTAGE; s++) {
            mbar_init(sb + s*8, 1);
            mbar_init(sb + 24 + s*8, 8);
        }
    }
    __syncthreads();

    // producer prologue: chunks 0,1
    if (tid == 0) {
        #pragma unroll
        for (int i = 0; i < 2; i++) {
            uint32_t st = sb + 1024 + i*STAGE_BYTES;
            uint32_t mb = sb + i*8;
            mbar_expect_tx(mb, STAGE_BYTES);
            bulk_g2s(st + STG_A_HI, aHiB + (size_t)i*TILE_BYTES, mb);
            bulk_g2s(st + STG_A_LO, aLoB + (size_t)i*TILE_BYTES, mb);
            bulk_g2s(st + STG_B_HI, bHiB + (size_t)i*TILE_BYTES, mb);
            bulk_g2s(st + STG_B_LO, bLoB + (size_t)i*TILE_BYTES, mb);
        }
    }

    // ldsm lane geometry (64B rows)
    const int laneR = lane & 15;
    const uint32_t laneC = (uint32_t)(lane >> 4) * 16;
    const uint32_t xorM  = (uint32_t)(laneR & 6) << 3;
    const uint32_t aBase = (uint32_t)(warp_m*64 + laneR) * 64;   // + mf*1024
    const uint32_t bBase = (uint32_t)(warp_n*32 + laneR) * 64;   // + g*1024

    float acc[4][4][4];
    #pragma unroll
    for (int i = 0; i < 4; i++)
        #pragma unroll
        for (int j = 0; j < 4; j++)
            #pragma unroll
            for (int k = 0; k < 4; k++) acc[i][j][k] = 0.0f;

    int stage_c = 0;
    for (int c = 0; c < NCHUNK; c++) {
        mbar_wait(sb + stage_c*8, (c/NSTAGE) & 1);

        if (tid == 0 && c + 2 < NCHUNK) {
            const int i = c + 2;
            int si = stage_c + 2; if (si >= NSTAGE) si -= NSTAGE;
            if (i >= NSTAGE)
                mbar_wait(sb + 24 + si*8, ((i/NSTAGE) - 1) & 1);
            uint32_t st = sb + 1024 + si*STAGE_BYTES;
            uint32_t mb = sb + si*8;
            mbar_expect_tx(mb, STAGE_BYTES);
            bulk_g2s(st + STG_A_HI, aHiB + (size_t)i*TILE_BYTES, mb);
            bulk_g2s(st + STG_A_LO, aLoB + (size_t)i*TILE_BYTES, mb);
            bulk_g2s(st + STG_B_HI, bHiB + (size_t)i*TILE_BYTES, mb);
            bulk_g2s(st + STG_B_LO, bLoB + (size_t)i*TILE_BYTES, mb);
        }

        const uint32_t stage = sb + 1024 + stage_c*STAGE_BYTES;
        #pragma unroll
        for (int kk = 0; kk < 2; kk++) {
            const uint32_t kbx = ((uint32_t)kk*32 + laneC) ^ xorM;

            uint32_t bhiF[4][2], bloF[4][2];
            #pragma unroll
            for (int g = 0; g < 2; g++) {
                uint32_t off = bBase + (uint32_t)g*1024 + kbx;
                uint32_t t0, t1, t2, t3;
                ldsm_x4(t0, t1, t2, t3, stage + STG_B_HI + off);
                bhiF[2*g][0] = t0; bhiF[2*g][1] = t2; bhiF[2*g+1][0] = t1; bhiF[2*g+1][1] = t3;
                ldsm_x4(t0, t1, t2, t3, stage + STG_B_LO + off);
                bloF[2*g][0] = t0; bloF[2*g][1] = t2; bloF[2*g+1][0] = t1; bloF[2*g+1][1] = t3;
            }
            uint32_t ahiF[2][4], aloF[2][4];
            {
                uint32_t off = aBase + kbx;
                ldsm_x4(ahiF[0][0], ahiF[0][1], ahiF[0][2], ahiF[0][3], stage + STG_A_HI + off);
                ldsm_x4(aloF[0][0], aloF[0][1], aloF[0][2], aloF[0][3], stage + STG_A_LO + off);
            }
            #pragma unroll
            for (int mf = 0; mf < 4; mf++) {
                const int cur = mf & 1, nxt = cur ^ 1;
                if (mf < 3) {
                    uint32_t off = aBase + (uint32_t)(mf+1)*1024 + kbx;
                    ldsm_x4(ahiF[nxt][0], ahiF[nxt][1], ahiF[nxt][2], ahiF[nxt][3],
                            stage + STG_A_HI + off);
                    ldsm_x4(aloF[nxt][0], aloF[nxt][1], aloF[nxt][2], aloF[nxt][3],
                            stage + STG_A_LO + off);
                }
                #pragma unroll
                for (int nf = 0; nf < 4; nf++)
                    mma16816(acc[mf][nf], ahiF[cur], bhiF[nf]);
                #pragma unroll
                for (int nf = 0; nf < 4; nf++)
                    mma16816(acc[mf][nf], ahiF[cur], bloF[nf]);
                #pragma unroll
                for (int nf = 0; nf < 4; nf++)
                    mma16816(acc[mf][nf], aloF[cur], bhiF[nf]);
            }
        }
        if (lane == 0) mbar_arrive(sb + 24 + stage_c*8);

        stage_c++; if (stage_c >= NSTAGE) stage_c -= NSTAGE;
    }

    // ---- epilogue ----
    const int g = lane >> 2, q = lane & 3;

    if (MODE == 1) {
        float rs[8];
        #pragma unroll
        for (int i = 0; i < 8; i++) rs[i] = 0.0f;
        #pragma unroll
        for (int mf = 0; mf < 4; mf++) {
            const size_t row0 = (size_t)arow0 + warp_m*64 + mf*16 + g;
            #pragma unroll
            for (int nf = 0; nf < 4; nf++) {
                const int col = ncol0 + warp_n*32 + nf*8 + q*2;
                const float r0 = __ldg(&rkb[col]);
                const float r1 = __ldg(&rkb[col+1]);
                float e0 = exp2f(fmaf(acc[mf][nf][0], EXP2_SCALE, r0));
                float e1 = exp2f(fmaf(acc[mf][nf][1], EXP2_SCALE, r1));
                float e2 = exp2f(fmaf(acc[mf][nf][2], EXP2_SCALE, r0));
                float e3 = exp2f(fmaf(acc[mf][nf][3], EXP2_SCALE, r1));
                *reinterpret_cast<float2*>(&outF[row0*S_ + col])     = make_float2(e0, e1);
                *reinterpret_cast<float2*>(&outF[(row0+8)*S_ + col]) = make_float2(e2, e3);
                rs[mf*2 + 0] += e0 + e1;
                rs[mf*2 + 1] += e2 + e3;
            }
        }
        #pragma unroll
        for (int i = 0; i < 8; i++) {
            rs[i] += __shfl_xor_sync(0xffffffffu, rs[i], 1);
            rs[i] += __shfl_xor_sync(0xffffffffu, rs[i], 2);
        }
        if (q == 0) {
            #pragma unroll
            for (int i = 0; i < 8; i++)
                s_rowsum[warp_m*64 + (i>>1)*16 + (i&1)*8 + g][warp_n] = rs[i];
        }
        __syncthreads();
        if (tid < 128) {
            float s = s_rowsum[tid][0] + s_rowsum[tid][1] + s_rowsum[tid][2] + s_rowsum[tid][3];
            psum[((size_t)arow0 + tid)*NT_ + blockIdx.x] = s;
        }

        // ---- last-finisher fused normalization ----
        const int blk = blockIdx.z * 16 + blockIdx.y;   // row block id (0..127)
        __threadfence();                                // release E + psum stores
        __syncthreads();
        if (tid == 0) {
            // atomicInc wraps to 0 on the 16th arrival -> self-resetting counter
            unsigned int old = atomicInc(&cnt[blk], NT_ - 1);
            s_last = (old == NT_ - 1) ? 1 : 0;
        }
        __syncthreads();
        if (s_last) {
            __threadfence();                            // acquire others' E + psum
            if (tid < 128) {
                const float* pr = &psum[((size_t)arow0 + tid) * NT_];
                float s = 0.0f;
                #pragma unroll
                for (int t = 0; t < NT_; t++) s += pr[t];
                s_inv[tid] = 1.0f / s;
            }
            __syncthreads();
            float4* strip = reinterpret_cast<float4*>(outF + (size_t)arow0 * S_);
            for (int i = tid; i < 128 * (S_/4); i += 256) {
                const float iv = s_inv[i >> 9];         // 512 float4 per row
                float4 v = strip[i];
                v.x *= iv; v.y *= iv; v.z *= iv; v.w *= iv;
                strip[i] = v;
            }
        }
    } else {
        // write u into BLOCKED hi/lo layout
        char* oh = (char*)outHi + (size_t)atile * 16 * TILE_BYTES;
        char* ol = (char*)outLo + (size_t)atile * 16 * TILE_BYTES;
        #pragma unroll
        for (int mf = 0; mf < 4; mf++) {
            const int r0 = warp_m*64 + mf*16 + g;       // row within tile
            #pragma unroll
            for (int nf = 0; nf < 4; nf++) {
                const int col = ncol0 + warp_n*32 + nf*8 + q*2;
                float v0 = acc[mf][nf][0];
                float v1 = acc[mf][nf][1];
                float v2 = acc[mf][nf][2];
                float v3 = acc[mf][nf][3];
                __nv_bfloat162 h01, l01, h23, l23;
                h01.x = __float2bfloat16(v0); h01.y = __float2bfloat16(v1);
                l01.x = __float2bfloat16(v0 - __bfloat162float(h01.x));
                l01.y = __float2bfloat16(v1 - __bfloat162float(h01.y));
                h23.x = __float2bfloat16(v2); h23.y = __float2bfloat16(v3);
                l23.x = __float2bfloat16(v2 - __bfloat162float(h23.x));
                l23.y = __float2bfloat16(v3 - __bfloat162float(h23.y));
                uint32_t o0 = blk_off(r0,     col);
                uint32_t o1 = blk_off(r0 + 8, col);
                *reinterpret_cast<__nv_bfloat162*>(oh + o0) = h01;
                *reinterpret_cast<__nv_bfloat162*>(ol + o0) = l01;
                *reinterpret_cast<__nv_bfloat162*>(oh + o1) = h23;
                *reinterpret_cast<__nv_bfloat162*>(ol + o1) = l23;
            }
        }
    }
}

// ---------------- launcher ----------------
extern "C" void kernel_launch(void* const* d_in, const int* in_sizes, int n_in,
                              void* d_out, int out_size)
{
    const float* x  = (const float*)d_in[0];
    const float* Wq = (const float*)d_in[1];
    const float* bq = (const float*)d_in[2];
    const float* Wk = (const float*)d_in[3];
    float* out = (float*)d_out;

    __nv_bfloat16 *xhi, *xlo, *m2hi, *m2lo, *uhi, *ulo;
    float *v2p, *rkp, *pptr;
    unsigned int *cntp;
    cudaGetSymbolAddress((void**)&xhi,  g_xhi);
    cudaGetSymbolAddress((void**)&xlo,  g_xlo);
    cudaGetSymbolAddress((void**)&m2hi, g_m2hi);
    cudaGetSymbolAddress((void**)&m2lo, g_m2lo);
    cudaGetSymbolAddress((void**)&uhi,  g_uhi);
    cudaGetSymbolAddress((void**)&ulo,  g_ulo);
    cudaGetSymbolAddress((void**)&v2p,  g_v2);
    cudaGetSymbolAddress((void**)&rkp,  g_rk);
    cudaGetSymbolAddress((void**)&pptr, g_psum);
    cudaGetSymbolAddress((void**)&cntp, g_cnt);

    cudaFuncSetAttribute(gemm_nt_kernel<0>, cudaFuncAttributeMaxDynamicSharedMemorySize, SMEM_DYN);
    cudaFuncSetAttribute(gemm_nt_kernel<1>, cudaFuncAttributeMaxDynamicSharedMemorySize, SMEM_DYN);

    // 1) preps (write blocked/swizzled layouts)
    v2_kernel<<<D_/8, 256>>>(Wk, bq, v2p);
    split_x_rk_kernel<<<B_*S_/4, 256>>>(x, v2p, xhi, xlo, rkp);
    dim3 mg(D_/32, D_/32);
    m2t_kernel<<<mg, 256>>>(Wk, Wq, m2hi, m2lo);

    // 2) u = x @ M2 (stored bf16 hi/lo, blocked)
    dim3 pg(D_/BN, (B_*S_)/BM);          // (4, 128)
    gemm_nt_kernel<0><<<pg, 256, SMEM_DYN>>>(xhi, xlo, m2hi, m2lo, nullptr, uhi, ulo, nullptr, nullptr, nullptr);

    // 3) scores + fused last-finisher normalize
    dim3 sg(S_/BN, S_/BM, B_);           // (16, 16, 8)
    gemm_nt_kernel<1><<<sg, 256, SMEM_DYN>>>(uhi, ulo, xhi, xlo, rkp, nullptr, nullptr, out, pptr, cntp);
}

// round 12
// speedup vs baseline: 1.0503x; 1.0503x over previous
#include <cuda_runtime.h>
#include <cuda_bf16.h>
#include <cstdint>
#include <math.h>

#define B_  8
#define S_  2048
#define D_  512
#define NT_ 16          // psum slots per row (S_/128 column tiles)

// ---- GEMM tile config ----
#define BM 128
#define BN 128
#define KC 32           // K elements per chunk (64B of bf16 per row)
#define NCHUNK (D_/KC)  // 16
#define NSTAGE 3

// blocked gmem: one (128-row tile, 32-col chunk) = 128*64B = 8KB, swizzled
#define TILE_BYTES 8192

// stage layout (bytes): four 128x32 bf16 tiles
#define STG_A_HI 0
#define STG_A_LO 8192
#define STG_B_HI 16384
#define STG_B_LO 24576
#define STAGE_BYTES 32768
// 2048 slack: dynamic smem base may not be 1024-aligned (R9/R10 overflow bug)
#define SMEM_DYN (2048 + NSTAGE*STAGE_BYTES)   // 100352

#define N_PROJ_CTAS 512      // proj role: ids [0, 512)
#define N_UTILES    128      // u row tiles

// (1/sqrt(512)) * log2(e)
#define EXP2_SCALE 0.06376070918938434f

// ---------------- scratch (device globals; blocked/swizzled layouts) --------
__device__ __nv_bfloat16 g_xhi[B_*S_*D_];   // blocked: [(tile*16+chunk)*8192 + swz]
__device__ __nv_bfloat16 g_xlo[B_*S_*D_];
__device__ __nv_bfloat16 g_m2hi[D_*D_];     // blocked: 4 tiles x 16 chunks
__device__ __nv_bfloat16 g_m2lo[D_*D_];
__device__ __nv_bfloat16 g_uhi[B_*S_*D_];   // blocked (written by proj role)
__device__ __nv_bfloat16 g_ulo[B_*S_*D_];
__device__ float         g_v2[D_];          // Wk @ bq
__device__ float         g_rk[B_*S_];       // (x[n].v2) * EXP2_SCALE
__device__ float         g_psum[B_*S_*NT_];
__device__ float         g_inv[B_*S_];
__device__ unsigned int  g_uflag[N_UTILES]; // u-tile ready flags (0..4; reset by last reader)
__device__ unsigned int  g_rcnt[N_UTILES];  // reader counters (atomicInc wrap 15)

// ---------------- helpers ----------------
__device__ __forceinline__ uint32_t smem_u32(const void* p) {
    uint32_t a;
    asm("{ .reg .u64 t; cvta.to.shared.u64 t, %1; cvt.u32.u64 %0, t; }" : "=r"(a) : "l"(p));
    return a;
}
__device__ __forceinline__ uint32_t swz64(uint32_t off) {
    return off ^ ((off >> 3) & 0x30);
}
__device__ __forceinline__ void mbar_init(uint32_t m, uint32_t cnt) {
    asm volatile("mbarrier.init.shared.b64 [%0], %1;" :: "r"(m), "r"(cnt) : "memory");
}
__device__ __forceinline__ void mbar_wait(uint32_t m, uint32_t parity) {
    asm volatile(
        "{\n\t.reg .pred P;\n\t"
        "W_%=:\n\t"
        "mbarrier.try_wait.parity.shared::cta.b64 P, [%0], %1, 10000000;\n\t"
        "@P bra.uni D_%=;\n\t"
        "bra.uni W_%=;\n\t"
        "D_%=:\n\t}"
        :: "r"(m), "r"(parity) : "memory");
}
__device__ __forceinline__ void mbar_arrive(uint32_t m) {
    asm volatile("mbarrier.arrive.shared.b64 _, [%0];" :: "r"(m) : "memory");
}
__device__ __forceinline__ void mbar_expect_tx(uint32_t m, uint32_t bytes) {
    asm volatile("mbarrier.arrive.expect_tx.shared.b64 _, [%0], %1;"
                 :: "r"(m), "r"(bytes) : "memory");
}
__device__ __forceinline__ void bulk_g2s(uint32_t dst, const void* src, uint32_t mbar) {
    asm volatile(
        "cp.async.bulk.shared::cluster.global.mbarrier::complete_tx::bytes [%0], [%1], %2, [%3];"
        :: "r"(dst), "l"(src), "r"((uint32_t)TILE_BYTES), "r"(mbar) : "memory");
}
__device__ __forceinline__ void ldsm_x4(uint32_t& r0, uint32_t& r1, uint32_t& r2, uint32_t& r3,
                                        uint32_t addr) {
    asm volatile("ldmatrix.sync.aligned.m8n8.x4.shared.b16 {%0,%1,%2,%3}, [%4];"
                 : "=r"(r0), "=r"(r1), "=r"(r2), "=r"(r3) : "r"(addr));
}
__device__ __forceinline__ void mma16816(float* c, const uint32_t* a, const uint32_t* b) {
    asm volatile(
        "mma.sync.aligned.m16n8k16.row.col.f32.bf16.bf16.f32 "
        "{%0,%1,%2,%3}, {%4,%5,%6,%7}, {%8,%9}, {%0,%1,%2,%3};"
        : "+f"(c[0]), "+f"(c[1]), "+f"(c[2]), "+f"(c[3])
        : "r"(a[0]), "r"(a[1]), "r"(a[2]), "r"(a[3]), "r"(b[0]), "r"(b[1]));
}

// blocked byte offset within a row-tile for (row in 0..127, col in 0..511)
__device__ __forceinline__ uint32_t blk_off(int r128, int col) {
    return (uint32_t)(col >> 5) * TILE_BYTES + swz64((uint32_t)(r128*64 + (col & 31)*2));
}

// ---------------- prep kernels ----------------
__global__ __launch_bounds__(256)
void v2_kernel(const float* __restrict__ Wk, const float* __restrict__ bq,
               float* __restrict__ v2)
{
    const int lane = threadIdx.x & 31;
    const int wrow = blockIdx.x * 8 + (threadIdx.x >> 5);
    float s = 0.0f;
    #pragma unroll
    for (int i = 0; i < 16; i++) {
        int d = i*32 + lane;
        s += Wk[(size_t)wrow*D_ + d] * bq[d];
    }
    #pragma unroll
    for (int o = 16; o > 0; o >>= 1) s += __shfl_xor_sync(0xffffffffu, s, o);
    if (lane == 0) v2[wrow] = s;
}

__global__ __launch_bounds__(256)
void split_x_rk_kernel(const float* __restrict__ in, const float* __restrict__ v2,
                       __nv_bfloat16* __restrict__ hi, __nv_bfloat16* __restrict__ lo,
                       float* __restrict__ rk)
{
    __shared__ float red[4][2];
    const int tid = threadIdx.x;
    const int rr  = tid >> 6;
    const int cg  = tid & 63;
    const int row = blockIdx.x * 4 + rr;
    const int col0 = cg * 8;

    const float* src = in + (size_t)row * D_ + col0;
    float4 v0 = *reinterpret_cast<const float4*>(src);
    float4 v1 = *reinterpret_cast<const float4*>(src + 4);
    float f[8] = {v0.x, v0.y, v0.z, v0.w, v1.x, v1.y, v1.z, v1.w};

    __nv_bfloat16 h[8], l[8];
    #pragma unroll
    for (int j = 0; j < 8; j++) {
        h[j] = __float2bfloat16(f[j]);
        l[j] = __float2bfloat16(f[j] - __bfloat162float(h[j]));
    }
    const size_t tbase = ((size_t)(row >> 7) * 16) * TILE_BYTES;
    const uint32_t off = blk_off(row & 127, col0);
    *reinterpret_cast<uint4*>((char*)hi + tbase + off) = *reinterpret_cast<uint4*>(h);
    *reinterpret_cast<uint4*>((char*)lo + tbase + off) = *reinterpret_cast<uint4*>(l);

    const float* w = v2 + col0;
    float local = 0.f;
    #pragma unroll
    for (int j = 0; j < 8; j++) local += f[j] * w[j];
    #pragma unroll
    for (int o = 16; o > 0; o >>= 1) local += __shfl_xor_sync(0xffffffffu, local, o);
    if ((tid & 31) == 0) red[rr][(cg >> 5)] = local;
    __syncthreads();
    if (cg == 0)
        rk[row] = (red[rr][0] + red[rr][1]) * EXP2_SCALE;
}

__global__ __launch_bounds__(256)
void m2t_kernel(const float* __restrict__ Wk, const float* __restrict__ Wq,
                __nv_bfloat16* __restrict__ m2hi, __nv_bfloat16* __restrict__ m2lo)
{
    __shared__ float sk[32][33];
    __shared__ float sq[32][33];
    const int tid = threadIdx.x;
    const int g0 = blockIdx.y * 32, f0 = blockIdx.x * 32;
    const int ty = tid >> 4, tx = tid & 15;

    float acc[2][2] = {{0.f,0.f},{0.f,0.f}};
    for (int d0 = 0; d0 < D_; d0 += 32) {
        #pragma unroll
        for (int p = 0; p < 4; p++) {
            int e = p*256 + tid;
            int r = e >> 5, c = e & 31;
            sk[r][c] = Wk[(size_t)(g0+r)*D_ + d0 + c];
            sq[r][c] = Wq[(size_t)(f0+r)*D_ + d0 + c];
        }
        __syncthreads();
        #pragma unroll
        for (int d = 0; d < 32; d++) {
            float k0v = sk[2*ty][d],   k1v = sk[2*ty+1][d];
            float q0v = sq[2*tx][d],   q1v = sq[2*tx+1][d];
            acc[0][0] = fmaf(k0v, q0v, acc[0][0]);
            acc[0][1] = fmaf(k0v, q1v, acc[0][1]);
            acc[1][0] = fmaf(k1v, q0v, acc[1][0]);
            acc[1][1] = fmaf(k1v, q1v, acc[1][1]);
        }
        __syncthreads();
    }
    #pragma unroll
    for (int i = 0; i < 2; i++)
        #pragma unroll
        for (int j = 0; j < 2; j++) {
            float v = acc[i][j];
            __nv_bfloat16 h = __float2bfloat16(v);
            __nv_bfloat16 l = __float2bfloat16(v - __bfloat162float(h));
            int g = g0 + 2*ty + i;
            int f = f0 + 2*tx + j;
            size_t tbase = ((size_t)(g >> 7) * 16) * TILE_BYTES;
            uint32_t off = blk_off(g & 127, f);
            *reinterpret_cast<__nv_bfloat16*>((char*)m2hi + tbase + off) = h;
            *reinterpret_cast<__nv_bfloat16*>((char*)m2lo + tbase + off) = l;
        }
}

// ---------------- fused proj+scores NT GEMM (1D grid, role by block id) -----
// ids [0,512):    proj  -> u = x@M2^T, stored bf16 hi/lo BLOCKED; releases uflag
// ids [512,2560): scores-> E = exp2(scale*(u x^T) + rk[n]) fp32 + row psums;
//                 waits on its u-tile flag before loading u.
__global__ __launch_bounds__(256, 2)
void fused_gemm_kernel(const __nv_bfloat16* __restrict__ xhi,
                       const __nv_bfloat16* __restrict__ xlo,
                       const __nv_bfloat16* __restrict__ m2hi,
                       const __nv_bfloat16* __restrict__ m2lo,
                       __nv_bfloat16* __restrict__ uhi,
                       __nv_bfloat16* __restrict__ ulo,
                       const float* __restrict__ rk,
                       float* __restrict__ outF,
                       float* __restrict__ psum,
                       unsigned int* uflag,
                       unsigned int* rcnt)
{
    extern __shared__ char smem_raw[];
    const uint32_t sb = (smem_u32(smem_raw) + 1023u) & ~1023u;
    __shared__ float s_rowsum[128][4];

    const int id     = blockIdx.x;
    const bool isProj = (id < N_PROJ_CTAS);
    const int tid    = threadIdx.x;
    const int lane   = tid & 31;
    const int wid    = tid >> 5;
    const int warp_m = wid & 1;      // 2 warps in M (64 rows each)
    const int warp_n = wid >> 1;     // 4 warps in N (32 cols each)

    int atile, btile, arow0, ncol0, sbx = 0, sbz = 0;
    const __nv_bfloat16 *aHiT, *aLoT, *bHiT, *bLoT;
    if (isProj) {
        const int bx = id & 3, by = id >> 2;
        atile = by; btile = bx;
        arow0 = by * BM; ncol0 = bx * BN;
        aHiT = xhi;  aLoT = xlo;  bHiT = m2hi; bLoT = m2lo;
    } else {
        const int sid = id - N_PROJ_CTAS;
        sbx = sid & 15;
        const int sby = (sid >> 4) & 15;
        sbz = sid >> 8;
        atile = sbz * 16 + sby;
        btile = sbz * 16 + sbx;
        arow0 = atile * BM; ncol0 = sbx * BN;
        aHiT = uhi;  aLoT = ulo;  bHiT = xhi;  bLoT = xlo;
    }
    const char* aHiB = (const char*)aHiT + (size_t)atile * 16 * TILE_BYTES;
    const char* aLoB = (const char*)aLoT + (size_t)atile * 16 * TILE_BYTES;
    const char* bHiB = (const char*)bHiT + (size_t)btile * 16 * TILE_BYTES;
    const char* bLoB = (const char*)bLoT + (size_t)btile * 16 * TILE_BYTES;
    const float* rkb = rk + (size_t)sbz * S_;

    // mbarriers: full[s] at sb+s*8 (count 1+tx), empty[s] at sb+24+s*8 (count 8)
    if (tid == 0) {
        #pragma unroll
        for (int s = 0; s < NSTAGE; s++) {
            mbar_init(sb + s*8, 1);
            mbar_init(sb + 24 + s*8, 8);
        }
    }
    __syncthreads();

    // producer prologue (scores role: wait for its u tile first)
    if (tid == 0) {
        if (!isProj) {
            volatile unsigned int* f = uflag + atile;
            while (*f < 4u) __nanosleep(64);
            __threadfence();                            // acquire u stores
            unsigned int old = atomicInc(&rcnt[atile], 15u);
            if (old == 15u) uflag[atile] = 0u;          // last reader resets
        }
        #pragma unroll
        for (int i = 0; i < 2; i++) {
            uint32_t st = sb + 1024 + i*STAGE_BYTES;
            uint32_t mb = sb + i*8;
            mbar_expect_tx(mb, STAGE_BYTES);
            bulk_g2s(st + STG_A_HI, aHiB + (size_t)i*TILE_BYTES, mb);
            bulk_g2s(st + STG_A_LO, aLoB + (size_t)i*TILE_BYTES, mb);
            bulk_g2s(st + STG_B_HI, bHiB + (size_t)i*TILE_BYTES, mb);
            bulk_g2s(st + STG_B_LO, bLoB + (size_t)i*TILE_BYTES, mb);
        }
    }

    // ldsm lane geometry (64B rows)
    const int laneR = lane & 15;
    const uint32_t laneC = (uint32_t)(lane >> 4) * 16;
    const uint32_t xorM  = (uint32_t)(laneR & 6) << 3;
    const uint32_t aBase = (uint32_t)(warp_m*64 + laneR) * 64;   // + mf*1024
    const uint32_t bBase = (uint32_t)(warp_n*32 + laneR) * 64;   // + g*1024

    float acc[4][4][4];
    #pragma unroll
    for (int i = 0; i < 4; i++)
        #pragma unroll
        for (int j = 0; j < 4; j++)
            #pragma unroll
            for (int k = 0; k < 4; k++) acc[i][j][k] = 0.0f;

    int stage_c = 0;
    for (int c = 0; c < NCHUNK; c++) {
        mbar_wait(sb + stage_c*8, (c/NSTAGE) & 1);

        if (tid == 0 && c + 2 < NCHUNK) {
            const int i = c + 2;
            int si = stage_c + 2; if (si >= NSTAGE) si -= NSTAGE;
            if (i >= NSTAGE)
                mbar_wait(sb + 24 + si*8, ((i/NSTAGE) - 1) & 1);
            uint32_t st = sb + 1024 + si*STAGE_BYTES;
            uint32_t mb = sb + si*8;
            mbar_expect_tx(mb, STAGE_BYTES);
            bulk_g2s(st + STG_A_HI, aHiB + (size_t)i*TILE_BYTES, mb);
            bulk_g2s(st + STG_A_LO, aLoB + (size_t)i*TILE_BYTES, mb);
            bulk_g2s(st + STG_B_HI, bHiB + (size_t)i*TILE_BYTES, mb);
            bulk_g2s(st + STG_B_LO, bLoB + (size_t)i*TILE_BYTES, mb);
        }

        const uint32_t stage = sb + 1024 + stage_c*STAGE_BYTES;
        #pragma unroll
        for (int kk = 0; kk < 2; kk++) {
            const uint32_t kbx = ((uint32_t)kk*32 + laneC) ^ xorM;

            uint32_t bhiF[4][2], bloF[4][2];
            #pragma unroll
            for (int g = 0; g < 2; g++) {
                uint32_t off = bBase + (uint32_t)g*1024 + kbx;
                uint32_t t0, t1, t2, t3;
                ldsm_x4(t0, t1, t2, t3, stage + STG_B_HI + off);
                bhiF[2*g][0] = t0; bhiF[2*g][1] = t2; bhiF[2*g+1][0] = t1; bhiF[2*g+1][1] = t3;
                ldsm_x4(t0, t1, t2, t3, stage + STG_B_LO + off);
                bloF[2*g][0] = t0; bloF[2*g][1] = t2; bloF[2*g+1][0] = t1; bloF[2*g+1][1] = t3;
            }
            uint32_t ahiF[2][4], aloF[2][4];
            {
                uint32_t off = aBase + kbx;
                ldsm_x4(ahiF[0][0], ahiF[0][1], ahiF[0][2], ahiF[0][3], stage + STG_A_HI + off);
                ldsm_x4(aloF[0][0], aloF[0][1], aloF[0][2], aloF[0][3], stage + STG_A_LO + off);
            }
            #pragma unroll
            for (int mf = 0; mf < 4; mf++) {
                const int cur = mf & 1, nxt = cur ^ 1;
                if (mf < 3) {
                    uint32_t off = aBase + (uint32_t)(mf+1)*1024 + kbx;
                    ldsm_x4(ahiF[nxt][0], ahiF[nxt][1], ahiF[nxt][2], ahiF[nxt][3],
                            stage + STG_A_HI + off);
                    ldsm_x4(aloF[nxt][0], aloF[nxt][1], aloF[nxt][2], aloF[nxt][3],
                            stage + STG_A_LO + off);
                }
                // hoisted empty-arrive: after this chunk's last ldsm (kk=1, mf=3)
                if (kk == 1 && mf == 3 && lane == 0)
                    mbar_arrive(sb + 24 + stage_c*8);
                #pragma unroll
                for (int nf = 0; nf < 4; nf++)
                    mma16816(acc[mf][nf], ahiF[cur], bhiF[nf]);
                #pragma unroll
                for (int nf = 0; nf < 4; nf++)
                    mma16816(acc[mf][nf], ahiF[cur], bloF[nf]);
                #pragma unroll
                for (int nf = 0; nf < 4; nf++)
                    mma16816(acc[mf][nf], aloF[cur], bhiF[nf]);
            }
        }
        stage_c++; if (stage_c >= NSTAGE) stage_c -= NSTAGE;
    }

    // ---- epilogue ----
    const int g = lane >> 2, q = lane & 3;

    if (!isProj) {
        float rs[8];
        #pragma unroll
        for (int i = 0; i < 8; i++) rs[i] = 0.0f;
        #pragma unroll
        for (int mf = 0; mf < 4; mf++) {
            const size_t row0 = (size_t)arow0 + warp_m*64 + mf*16 + g;
            #pragma unroll
            for (int nf = 0; nf < 4; nf++) {
                const int col = ncol0 + warp_n*32 + nf*8 + q*2;
                const float r0 = __ldg(&rkb[col]);
                const float r1 = __ldg(&rkb[col+1]);
                float e0 = exp2f(fmaf(acc[mf][nf][0], EXP2_SCALE, r0));
                float e1 = exp2f(fmaf(acc[mf][nf][1], EXP2_SCALE, r1));
                float e2 = exp2f(fmaf(acc[mf][nf][2], EXP2_SCALE, r0));
                float e3 = exp2f(fmaf(acc[mf][nf][3], EXP2_SCALE, r1));
                *reinterpret_cast<float2*>(&outF[row0*S_ + col])     = make_float2(e0, e1);
                *reinterpret_cast<float2*>(&outF[(row0+8)*S_ + col]) = make_float2(e2, e3);
                rs[mf*2 + 0] += e0 + e1;
                rs[mf*2 + 1] += e2 + e3;
            }
        }
        #pragma unroll
        for (int i = 0; i < 8; i++) {
            rs[i] += __shfl_xor_sync(0xffffffffu, rs[i], 1);
            rs[i] += __shfl_xor_sync(0xffffffffu, rs[i], 2);
        }
        if (q == 0) {
            #pragma unroll
            for (int i = 0; i < 8; i++)
                s_rowsum[warp_m*64 + (i>>1)*16 + (i&1)*8 + g][warp_n] = rs[i];
        }
        __syncthreads();
        if (tid < 128) {
            float s = s_rowsum[tid][0] + s_rowsum[tid][1] + s_rowsum[tid][2] + s_rowsum[tid][3];
            psum[((size_t)arow0 + tid)*NT_ + sbx] = s;
        }
    } else {
        // write u into BLOCKED hi/lo layout, then release the tile flag
        char* oh = (char*)uhi + (size_t)atile * 16 * TILE_BYTES;
        char* ol = (char*)ulo + (size_t)atile * 16 * TILE_BYTES;
        #pragma unroll
        for (int mf = 0; mf < 4; mf++) {
            const int r0 = warp_m*64 + mf*16 + g;       // row within tile
            #pragma unroll
            for (int nf = 0; nf < 4; nf++) {
                const int col = ncol0 + warp_n*32 + nf*8 + q*2;
                float v0 = acc[mf][nf][0];
                float v1 = acc[mf][nf][1];
                float v2 = acc[mf][nf][2];
                float v3 = acc[mf][nf][3];
                __nv_bfloat162 h01, l01, h23, l23;
                h01.x = __float2bfloat16(v0); h01.y = __float2bfloat16(v1);
                l01.x = __float2bfloat16(v0 - __bfloat162float(h01.x));
                l01.y = __float2bfloat16(v1 - __bfloat162float(h01.y));
                h23.x = __float2bfloat16(v2); h23.y = __float2bfloat16(v3);
                l23.x = __float2bfloat16(v2 - __bfloat162float(h23.x));
                l23.y = __float2bfloat16(v3 - __bfloat162float(h23.y));
                uint32_t o0 = blk_off(r0,     col);
                uint32_t o1 = blk_off(r0 + 8, col);
                *reinterpret_cast<__nv_bfloat162*>(oh + o0) = h01;
                *reinterpret_cast<__nv_bfloat162*>(ol + o0) = l01;
                *reinterpret_cast<__nv_bfloat162*>(oh + o1) = h23;
                *reinterpret_cast<__nv_bfloat162*>(ol + o1) = l23;
            }
        }
        __threadfence();                 // release this CTA's u stores
        __syncthreads();                 // all threads fenced
        if (tid == 0) atomicAdd(&uflag[atile], 1u);
    }
}

// ---------------- row-sum inverse + flat normalize ----------------
__global__ __launch_bounds__(256)
void invsum_kernel(const float* __restrict__ psum, float* __restrict__ inv)
{
    const int row = blockIdx.x * 256 + threadIdx.x;
    const float4* p = reinterpret_cast<const float4*>(psum + (size_t)row * NT_);
    float4 a = p[0], b = p[1], c = p[2], d = p[3];
    float s = ((a.x+a.y)+(a.z+a.w)) + ((b.x+b.y)+(b.z+b.w))
            + ((c.x+c.y)+(c.z+c.w)) + ((d.x+d.y)+(d.z+d.w));
    inv[row] = 1.0f / s;
}

__global__ __launch_bounds__(256)
void normalize_kernel(float* __restrict__ out, const float* __restrict__ inv)
{
    const size_t i = (size_t)blockIdx.x * 256 + threadIdx.x;   // float4 index
    const float iv = __ldg(&inv[i >> 9]);                      // 512 float4 per row
    float4 v = reinterpret_cast<float4*>(out)[i];
    v.x *= iv; v.y *= iv; v.z *= iv; v.w *= iv;
    reinterpret_cast<float4*>(out)[i] = v;
}

// ---------------- launcher ----------------
extern "C" void kernel_launch(void* const* d_in, const int* in_sizes, int n_in,
                              void* d_out, int out_size)
{
    const float* x  = (const float*)d_in[0];
    const float* Wq = (const float*)d_in[1];
    const float* bq = (const float*)d_in[2];
    const float* Wk = (const float*)d_in[3];
    float* out = (float*)d_out;

    __nv_bfloat16 *xhi, *xlo, *m2hi, *m2lo, *uhi, *ulo;
    float *v2p, *rkp, *pptr, *invp;
    unsigned int *uflagp, *rcntp;
    cudaGetSymbolAddress((void**)&xhi,  g_xhi);
    cudaGetSymbolAddress((void**)&xlo,  g_xlo);
    cudaGetSymbolAddress((void**)&m2hi, g_m2hi);
    cudaGetSymbolAddress((void**)&m2lo, g_m2lo);
    cudaGetSymbolAddress((void**)&uhi,  g_uhi);
    cudaGetSymbolAddress((void**)&ulo,  g_ulo);
    cudaGetSymbolAddress((void**)&v2p,  g_v2);
    cudaGetSymbolAddress((void**)&rkp,  g_rk);
    cudaGetSymbolAddress((void**)&pptr, g_psum);
    cudaGetSymbolAddress((void**)&invp, g_inv);
    cudaGetSymbolAddress((void**)&uflagp, g_uflag);
    cudaGetSymbolAddress((void**)&rcntp,  g_rcnt);

    cudaFuncSetAttribute(fused_gemm_kernel, cudaFuncAttributeMaxDynamicSharedMemorySize, SMEM_DYN);

    // 1) preps (write blocked/swizzled layouts)
    v2_kernel<<<D_/8, 256>>>(Wk, bq, v2p);
    split_x_rk_kernel<<<B_*S_/4, 256>>>(x, v2p, xhi, xlo, rkp);
    dim3 mg(D_/32, D_/32);
    m2t_kernel<<<mg, 256>>>(Wk, Wq, m2hi, m2lo);

    // 2) fused proj + scores (proj CTAs first in launch order)
    fused_gemm_kernel<<<N_PROJ_CTAS + S_/BN * S_/BM * B_, 256, SMEM_DYN>>>(
        xhi, xlo, m2hi, m2lo, uhi, ulo, rkp, out, pptr, uflagp, rcntp);

    // 3) normalize
    invsum_kernel<<<B_*S_/256, 256>>>(pptr, invp);
    normalize_kernel<<<(B_*S_*(S_/4))/256, 256>>>(out, invp);
}

// round 13
// speedup vs baseline: 1.1244x; 1.0706x over previous
#include <cuda_runtime.h>
#include <cuda_bf16.h>
#include <cstdint>
#include <math.h>

#define B_  8
#define S_  2048
#define D_  512
#define NT_ 16          // psum slots per row (S_/128 column tiles)

// ---- GEMM tile config ----
#define BM 128
#define BN 128
#define KC 32           // K elements per chunk (64B of bf16 per row)
#define NCHUNK (D_/KC)  // 16
#define NSTAGE 3

// blocked gmem: one (128-row tile, 32-col chunk) = 128*64B = 8KB, swizzled
#define TILE_BYTES 8192

// stage layout (bytes): four 128x32 bf16 tiles
#define STG_A_HI 0
#define STG_A_LO 8192
#define STG_B_HI 16384
#define STG_B_LO 24576
#define STAGE_BYTES 32768
// 2048 slack: dynamic smem base may not be 1024-aligned (R9/R10 overflow bug)
#define SMEM_DYN (2048 + NSTAGE*STAGE_BYTES)   // 100352

#define N_PROJ_CTAS 512      // proj role: ids [0, 512)
#define N_UTILES    128      // u row tiles / scores row blocks

// (1/sqrt(512)) * log2(e)
#define EXP2_SCALE 0.06376070918938434f

// ---------------- scratch (device globals; blocked/swizzled layouts) --------
__device__ __nv_bfloat16 g_xhi[B_*S_*D_];   // blocked: [(tile*16+chunk)*8192 + swz]
__device__ __nv_bfloat16 g_xlo[B_*S_*D_];
__device__ __nv_bfloat16 g_m2hi[D_*D_];     // blocked: 4 tiles x 16 chunks
__device__ __nv_bfloat16 g_m2lo[D_*D_];
__device__ __nv_bfloat16 g_uhi[B_*S_*D_];   // blocked (written by proj role)
__device__ __nv_bfloat16 g_ulo[B_*S_*D_];
__device__ float         g_v2[D_];          // Wk @ bq
__device__ float         g_rk[B_*S_];       // (x[n].v2) * EXP2_SCALE
__device__ float         g_psum[B_*S_*NT_];
__device__ unsigned int  g_uflag[N_UTILES]; // u-tile ready flags (reset by last reader)
__device__ unsigned int  g_rcnt[N_UTILES];  // u-tile reader counters (atomicInc wrap 15)
__device__ unsigned int  g_scnt[N_UTILES];  // scores row-block psum arrivals (reset by last reader)
__device__ unsigned int  g_srd[N_UTILES];   // scores row-block reader counters (wrap 15)

// ---------------- helpers ----------------
__device__ __forceinline__ uint32_t smem_u32(const void* p) {
    uint32_t a;
    asm("{ .reg .u64 t; cvta.to.shared.u64 t, %1; cvt.u32.u64 %0, t; }" : "=r"(a) : "l"(p));
    return a;
}
__device__ __forceinline__ uint32_t swz64(uint32_t off) {
    return off ^ ((off >> 3) & 0x30);
}
__device__ __forceinline__ void mbar_init(uint32_t m, uint32_t cnt) {
    asm volatile("mbarrier.init.shared.b64 [%0], %1;" :: "r"(m), "r"(cnt) : "memory");
}
__device__ __forceinline__ void mbar_wait(uint32_t m, uint32_t parity) {
    asm volatile(
        "{\n\t.reg .pred P;\n\t"
        "W_%=:\n\t"
        "mbarrier.try_wait.parity.shared::cta.b64 P, [%0], %1, 10000000;\n\t"
        "@P bra.uni D_%=;\n\t"
        "bra.uni W_%=;\n\t"
        "D_%=:\n\t}"
        :: "r"(m), "r"(parity) : "memory");
}
__device__ __forceinline__ void mbar_arrive(uint32_t m) {
    asm volatile("mbarrier.arrive.shared.b64 _, [%0];" :: "r"(m) : "memory");
}
__device__ __forceinline__ void mbar_expect_tx(uint32_t m, uint32_t bytes) {
    asm volatile("mbarrier.arrive.expect_tx.shared.b64 _, [%0], %1;"
                 :: "r"(m), "r"(bytes) : "memory");
}
__device__ __forceinline__ void bulk_g2s(uint32_t dst, const void* src, uint32_t mbar) {
    asm volatile(
        "cp.async.bulk.shared::cluster.global.mbarrier::complete_tx::bytes [%0], [%1], %2, [%3];"
        :: "r"(dst), "l"(src), "r"((uint32_t)TILE_BYTES), "r"(mbar) : "memory");
}
__device__ __forceinline__ void ldsm_x4(uint32_t& r0, uint32_t& r1, uint32_t& r2, uint32_t& r3,
                                        uint32_t addr) {
    asm volatile("ldmatrix.sync.aligned.m8n8.x4.shared.b16 {%0,%1,%2,%3}, [%4];"
                 : "=r"(r0), "=r"(r1), "=r"(r2), "=r"(r3) : "r"(addr));
}
__device__ __forceinline__ void mma16816(float* c, const uint32_t* a, const uint32_t* b) {
    asm volatile(
        "mma.sync.aligned.m16n8k16.row.col.f32.bf16.bf16.f32 "
        "{%0,%1,%2,%3}, {%4,%5,%6,%7}, {%8,%9}, {%0,%1,%2,%3};"
        : "+f"(c[0]), "+f"(c[1]), "+f"(c[2]), "+f"(c[3])
        : "r"(a[0]), "r"(a[1]), "r"(a[2]), "r"(a[3]), "r"(b[0]), "r"(b[1]));
}

// blocked byte offset within a row-tile for (row in 0..127, col in 0..511)
__device__ __forceinline__ uint32_t blk_off(int r128, int col) {
    return (uint32_t)(col >> 5) * TILE_BYTES + swz64((uint32_t)(r128*64 + (col & 31)*2));
}

// ---------------- prep kernels ----------------
__global__ __launch_bounds__(256)
void v2_kernel(const float* __restrict__ Wk, const float* __restrict__ bq,
               float* __restrict__ v2)
{
    const int lane = threadIdx.x & 31;
    const int wrow = blockIdx.x * 8 + (threadIdx.x >> 5);
    float s = 0.0f;
    #pragma unroll
    for (int i = 0; i < 16; i++) {
        int d = i*32 + lane;
        s += Wk[(size_t)wrow*D_ + d] * bq[d];
    }
    #pragma unroll
    for (int o = 16; o > 0; o >>= 1) s += __shfl_xor_sync(0xffffffffu, s, o);
    if (lane == 0) v2[wrow] = s;
}

__global__ __launch_bounds__(256)
void split_x_rk_kernel(const float* __restrict__ in, const float* __restrict__ v2,
                       __nv_bfloat16* __restrict__ hi, __nv_bfloat16* __restrict__ lo,
                       float* __restrict__ rk)
{
    __shared__ float red[4][2];
    const int tid = threadIdx.x;
    const int rr  = tid >> 6;
    const int cg  = tid & 63;
    const int row = blockIdx.x * 4 + rr;
    const int col0 = cg * 8;

    const float* src = in + (size_t)row * D_ + col0;
    float4 v0 = *reinterpret_cast<const float4*>(src);
    float4 v1 = *reinterpret_cast<const float4*>(src + 4);
    float f[8] = {v0.x, v0.y, v0.z, v0.w, v1.x, v1.y, v1.z, v1.w};

    __nv_bfloat16 h[8], l[8];
    #pragma unroll
    for (int j = 0; j < 8; j++) {
        h[j] = __float2bfloat16(f[j]);
        l[j] = __float2bfloat16(f[j] - __bfloat162float(h[j]));
    }
    const size_t tbase = ((size_t)(row >> 7) * 16) * TILE_BYTES;
    const uint32_t off = blk_off(row & 127, col0);
    *reinterpret_cast<uint4*>((char*)hi + tbase + off) = *reinterpret_cast<uint4*>(h);
    *reinterpret_cast<uint4*>((char*)lo + tbase + off) = *reinterpret_cast<uint4*>(l);

    const float* w = v2 + col0;
    float local = 0.f;
    #pragma unroll
    for (int j = 0; j < 8; j++) local += f[j] * w[j];
    #pragma unroll
    for (int o = 16; o > 0; o >>= 1) local += __shfl_xor_sync(0xffffffffu, local, o);
    if ((tid & 31) == 0) red[rr][(cg >> 5)] = local;
    __syncthreads();
    if (cg == 0)
        rk[row] = (red[rr][0] + red[rr][1]) * EXP2_SCALE;
}

__global__ __launch_bounds__(256)
void m2t_kernel(const float* __restrict__ Wk, const float* __restrict__ Wq,
                __nv_bfloat16* __restrict__ m2hi, __nv_bfloat16* __restrict__ m2lo)
{
    __shared__ float sk[32][33];
    __shared__ float sq[32][33];
    const int tid = threadIdx.x;
    const int g0 = blockIdx.y * 32, f0 = blockIdx.x * 32;
    const int ty = tid >> 4, tx = tid & 15;

    float acc[2][2] = {{0.f,0.f},{0.f,0.f}};
    for (int d0 = 0; d0 < D_; d0 += 32) {
        #pragma unroll
        for (int p = 0; p < 4; p++) {
            int e = p*256 + tid;
            int r = e >> 5, c = e & 31;
            sk[r][c] = Wk[(size_t)(g0+r)*D_ + d0 + c];
            sq[r][c] = Wq[(size_t)(f0+r)*D_ + d0 + c];
        }
        __syncthreads();
        #pragma unroll
        for (int d = 0; d < 32; d++) {
            float k0v = sk[2*ty][d],   k1v = sk[2*ty+1][d];
            float q0v = sq[2*tx][d],   q1v = sq[2*tx+1][d];
            acc[0][0] = fmaf(k0v, q0v, acc[0][0]);
            acc[0][1] = fmaf(k0v, q1v, acc[0][1]);
            acc[1][0] = fmaf(k1v, q0v, acc[1][0]);
            acc[1][1] = fmaf(k1v, q1v, acc[1][1]);
        }
        __syncthreads();
    }
    #pragma unroll
    for (int i = 0; i < 2; i++)
        #pragma unroll
        for (int j = 0; j < 2; j++) {
            float v = acc[i][j];
            __nv_bfloat16 h = __float2bfloat16(v);
            __nv_bfloat16 l = __float2bfloat16(v - __bfloat162float(h));
            int g = g0 + 2*ty + i;
            int f = f0 + 2*tx + j;
            size_t tbase = ((size_t)(g >> 7) * 16) * TILE_BYTES;
            uint32_t off = blk_off(g & 127, f);
            *reinterpret_cast<__nv_bfloat16*>((char*)m2hi + tbase + off) = h;
            *reinterpret_cast<__nv_bfloat16*>((char*)m2lo + tbase + off) = l;
        }
}

// ---------------- fused proj+scores+softmax NT GEMM (1D grid) ---------------
// ids [0,512):    proj  -> u = x@M2^T, bf16 hi/lo BLOCKED; releases uflag
// ids [512,2560): scores-> e = exp2(scale*(u x^T) + rk[n]) kept in regs;
//                 psum exchange with sibling CTAs, then writes alpha = e/sum
//                 directly (single write of the output, no normalize pass).
__global__ __launch_bounds__(256, 2)
void fused_gemm_kernel(const __nv_bfloat16* __restrict__ xhi,
                       const __nv_bfloat16* __restrict__ xlo,
                       const __nv_bfloat16* __restrict__ m2hi,
                       const __nv_bfloat16* __restrict__ m2lo,
                       __nv_bfloat16* __restrict__ uhi,
                       __nv_bfloat16* __restrict__ ulo,
                       const float* __restrict__ rk,
                       float* __restrict__ outF,
                       float* __restrict__ psum,
                       unsigned int* uflag,
                       unsigned int* rcnt,
                       unsigned int* scnt,
                       unsigned int* srd)
{
    extern __shared__ char smem_raw[];
    const uint32_t sb = (smem_u32(smem_raw) + 1023u) & ~1023u;
    __shared__ float s_rowsum[128][4];
    __shared__ float s_inv[128];

    const int id     = blockIdx.x;
    const bool isProj = (id < N_PROJ_CTAS);
    const int tid    = threadIdx.x;
    const int lane   = tid & 31;
    const int wid    = tid >> 5;
    const int warp_m = wid & 1;      // 2 warps in M (64 rows each)
    const int warp_n = wid >> 1;     // 4 warps in N (32 cols each)

    int atile, btile, arow0, ncol0, sbx = 0, sbz = 0;
    const __nv_bfloat16 *aHiT, *aLoT, *bHiT, *bLoT;
    if (isProj) {
        const int bx = id & 3, by = id >> 2;
        atile = by; btile = bx;
        arow0 = by * BM; ncol0 = bx * BN;
        aHiT = xhi;  aLoT = xlo;  bHiT = m2hi; bLoT = m2lo;
    } else {
        const int sid = id - N_PROJ_CTAS;
        sbx = sid & 15;
        const int sby = (sid >> 4) & 15;
        sbz = sid >> 8;
        atile = sbz * 16 + sby;
        btile = sbz * 16 + sbx;
        arow0 = atile * BM; ncol0 = sbx * BN;
        aHiT = uhi;  aLoT = ulo;  bHiT = xhi;  bLoT = xlo;
    }
    const char* aHiB = (const char*)aHiT + (size_t)atile * 16 * TILE_BYTES;
    const char* aLoB = (const char*)aLoT + (size_t)atile * 16 * TILE_BYTES;
    const char* bHiB = (const char*)bHiT + (size_t)btile * 16 * TILE_BYTES;
    const char* bLoB = (const char*)bLoT + (size_t)btile * 16 * TILE_BYTES;
    const float* rkb = rk + (size_t)sbz * S_;

    // mbarriers: full[s] at sb+s*8 (count 1+tx), empty[s] at sb+24+s*8 (count 8)
    if (tid == 0) {
        #pragma unroll
        for (int s = 0; s < NSTAGE; s++) {
            mbar_init(sb + s*8, 1);
            mbar_init(sb + 24 + s*8, 8);
        }
    }
    __syncthreads();

    // producer prologue (scores role: wait for its u tile first)
    if (tid == 0) {
        if (!isProj) {
            volatile unsigned int* f = uflag + atile;
            while (*f < 4u) __nanosleep(64);
            __threadfence();                            // acquire u stores
            unsigned int old = atomicInc(&rcnt[atile], 15u);
            if (old == 15u) uflag[atile] = 0u;          // last reader resets
        }
        #pragma unroll
        for (int i = 0; i < 2; i++) {
            uint32_t st = sb + 1024 + i*STAGE_BYTES;
            uint32_t mb = sb + i*8;
            mbar_expect_tx(mb, STAGE_BYTES);
            bulk_g2s(st + STG_A_HI, aHiB + (size_t)i*TILE_BYTES, mb);
            bulk_g2s(st + STG_A_LO, aLoB + (size_t)i*TILE_BYTES, mb);
            bulk_g2s(st + STG_B_HI, bHiB + (size_t)i*TILE_BYTES, mb);
            bulk_g2s(st + STG_B_LO, bLoB + (size_t)i*TILE_BYTES, mb);
        }
    }

    // ldsm lane geometry (64B rows)
    const int laneR = lane & 15;
    const uint32_t laneC = (uint32_t)(lane >> 4) * 16;
    const uint32_t xorM  = (uint32_t)(laneR & 6) << 3;
    const uint32_t aBase = (uint32_t)(warp_m*64 + laneR) * 64;   // + mf*1024
    const uint32_t bBase = (uint32_t)(warp_n*32 + laneR) * 64;   // + g*1024

    float acc[4][4][4];
    #pragma unroll
    for (int i = 0; i < 4; i++)
        #pragma unroll
        for (int j = 0; j < 4; j++)
            #pragma unroll
            for (int k = 0; k < 4; k++) acc[i][j][k] = 0.0f;

    int stage_c = 0;
    for (int c = 0; c < NCHUNK; c++) {
        mbar_wait(sb + stage_c*8, (c/NSTAGE) & 1);

        if (tid == 0 && c + 2 < NCHUNK) {
            const int i = c + 2;
            int si = stage_c + 2; if (si >= NSTAGE) si -= NSTAGE;
            if (i >= NSTAGE)
                mbar_wait(sb + 24 + si*8, ((i/NSTAGE) - 1) & 1);
            uint32_t st = sb + 1024 + si*STAGE_BYTES;
            uint32_t mb = sb + si*8;
            mbar_expect_tx(mb, STAGE_BYTES);
            bulk_g2s(st + STG_A_HI, aHiB + (size_t)i*TILE_BYTES, mb);
            bulk_g2s(st + STG_A_LO, aLoB + (size_t)i*TILE_BYTES, mb);
            bulk_g2s(st + STG_B_HI, bHiB + (size_t)i*TILE_BYTES, mb);
            bulk_g2s(st + STG_B_LO, bLoB + (size_t)i*TILE_BYTES, mb);
        }

        const uint32_t stage = sb + 1024 + stage_c*STAGE_BYTES;
        #pragma unroll
        for (int kk = 0; kk < 2; kk++) {
            const uint32_t kbx = ((uint32_t)kk*32 + laneC) ^ xorM;

            uint32_t bhiF[4][2], bloF[4][2];
            #pragma unroll
            for (int g = 0; g < 2; g++) {
                uint32_t off = bBase + (uint32_t)g*1024 + kbx;
                uint32_t t0, t1, t2, t3;
                ldsm_x4(t0, t1, t2, t3, stage + STG_B_HI + off);
                bhiF[2*g][0] = t0; bhiF[2*g][1] = t2; bhiF[2*g+1][0] = t1; bhiF[2*g+1][1] = t3;
                ldsm_x4(t0, t1, t2, t3, stage + STG_B_LO + off);
                bloF[2*g][0] = t0; bloF[2*g][1] = t2; bloF[2*g+1][0] = t1; bloF[2*g+1][1] = t3;
            }
            uint32_t ahiF[2][4], aloF[2][4];
            {
                uint32_t off = aBase + kbx;
                ldsm_x4(ahiF[0][0], ahiF[0][1], ahiF[0][2], ahiF[0][3], stage + STG_A_HI + off);
                ldsm_x4(aloF[0][0], aloF[0][1], aloF[0][2], aloF[0][3], stage + STG_A_LO + off);
            }
            #pragma unroll
            for (int mf = 0; mf < 4; mf++) {
                const int cur = mf & 1, nxt = cur ^ 1;
                if (mf < 3) {
                    uint32_t off = aBase + (uint32_t)(mf+1)*1024 + kbx;
                    ldsm_x4(ahiF[nxt][0], ahiF[nxt][1], ahiF[nxt][2], ahiF[nxt][3],
                            stage + STG_A_HI + off);
                    ldsm_x4(aloF[nxt][0], aloF[nxt][1], aloF[nxt][2], aloF[nxt][3],
                            stage + STG_A_LO + off);
                }
                // hoisted empty-arrive: after this chunk's last ldsm (kk=1, mf=3)
                if (kk == 1 && mf == 3 && lane == 0)
                    mbar_arrive(sb + 24 + stage_c*8);
                #pragma unroll
                for (int nf = 0; nf < 4; nf++)
                    mma16816(acc[mf][nf], ahiF[cur], bhiF[nf]);
                #pragma unroll
                for (int nf = 0; nf < 4; nf++)
                    mma16816(acc[mf][nf], ahiF[cur], bloF[nf]);
                #pragma unroll
                for (int nf = 0; nf < 4; nf++)
                    mma16816(acc[mf][nf], aloF[cur], bhiF[nf]);
            }
        }
        stage_c++; if (stage_c >= NSTAGE) stage_c -= NSTAGE;
    }

    // ---- epilogue ----
    const int g = lane >> 2, q = lane & 3;

    if (!isProj) {
        // 1) e = exp2(...) in-place into acc; accumulate row sums
        float rs[8];
        #pragma unroll
        for (int i = 0; i < 8; i++) rs[i] = 0.0f;
        #pragma unroll
        for (int mf = 0; mf < 4; mf++) {
            #pragma unroll
            for (int nf = 0; nf < 4; nf++) {
                const int col = ncol0 + warp_n*32 + nf*8 + q*2;
                const float r0 = __ldg(&rkb[col]);
                const float r1 = __ldg(&rkb[col+1]);
                acc[mf][nf][0] = exp2f(fmaf(acc[mf][nf][0], EXP2_SCALE, r0));
                acc[mf][nf][1] = exp2f(fmaf(acc[mf][nf][1], EXP2_SCALE, r1));
                acc[mf][nf][2] = exp2f(fmaf(acc[mf][nf][2], EXP2_SCALE, r0));
                acc[mf][nf][3] = exp2f(fmaf(acc[mf][nf][3], EXP2_SCALE, r1));
                rs[mf*2 + 0] += acc[mf][nf][0] + acc[mf][nf][1];
                rs[mf*2 + 1] += acc[mf][nf][2] + acc[mf][nf][3];
            }
        }
        #pragma unroll
        for (int i = 0; i < 8; i++) {
            rs[i] += __shfl_xor_sync(0xffffffffu, rs[i], 1);
            rs[i] += __shfl_xor_sync(0xffffffffu, rs[i], 2);
        }
        if (q == 0) {
            #pragma unroll
            for (int i = 0; i < 8; i++)
                s_rowsum[warp_m*64 + (i>>1)*16 + (i&1)*8 + g][warp_n] = rs[i];
        }
        __syncthreads();
        if (tid < 128) {
            float s = s_rowsum[tid][0] + s_rowsum[tid][1] + s_rowsum[tid][2] + s_rowsum[tid][3];
            psum[((size_t)arow0 + tid)*NT_ + sbx] = s;
        }

        // 2) release psum, arrive on row-block counter
        __threadfence();
        __syncthreads();
        if (tid == 0) {
            atomicAdd(&scnt[atile], 1u);
            // 3) spin until all 16 siblings posted their psum
            volatile unsigned int* f = scnt + atile;
            while (*f < (unsigned)NT_) __nanosleep(32);
        }
        __syncthreads();
        __threadfence();                    // acquire siblings' psum
        if (tid < 128) {
            const float* pr = &psum[((size_t)arow0 + tid) * NT_];
            float s = 0.0f;
            #pragma unroll
            for (int t = 0; t < NT_; t++) s += pr[t];
            s_inv[tid] = 1.0f / s;
        }
        __syncthreads();

        // 4) single normalized write of alpha
        #pragma unroll
        for (int mf = 0; mf < 4; mf++) {
            const int r0 = warp_m*64 + mf*16 + g;
            const float iv0 = s_inv[r0];
            const float iv1 = s_inv[r0 + 8];
            const size_t grow = (size_t)arow0 + r0;
            #pragma unroll
            for (int nf = 0; nf < 4; nf++) {
                const int col = ncol0 + warp_n*32 + nf*8 + q*2;
                *reinterpret_cast<float2*>(&outF[grow*S_ + col]) =
                    make_float2(acc[mf][nf][0]*iv0, acc[mf][nf][1]*iv0);
                *reinterpret_cast<float2*>(&outF[(grow+8)*S_ + col]) =
                    make_float2(acc[mf][nf][2]*iv1, acc[mf][nf][3]*iv1);
            }
        }

        // 5) self-reset for graph replay: last reader zeroes scnt
        if (tid == 0) {
            unsigned int old = atomicInc(&srd[atile], 15u);
            if (old == 15u) scnt[atile] = 0u;
        }
    } else {
        // write u into BLOCKED hi/lo layout, then release the tile flag
        char* oh = (char*)uhi + (size_t)atile * 16 * TILE_BYTES;
        char* ol = (char*)ulo + (size_t)atile * 16 * TILE_BYTES;
        #pragma unroll
        for (int mf = 0; mf < 4; mf++) {
            const int r0 = warp_m*64 + mf*16 + g;       // row within tile
            #pragma unroll
            for (int nf = 0; nf < 4; nf++) {
                const int col = ncol0 + warp_n*32 + nf*8 + q*2;
                float v0 = acc[mf][nf][0];
                float v1 = acc[mf][nf][1];
                float v2 = acc[mf][nf][2];
                float v3 = acc[mf][nf][3];
                __nv_bfloat162 h01, l01, h23, l23;
                h01.x = __float2bfloat16(v0); h01.y = __float2bfloat16(v1);
                l01.x = __float2bfloat16(v0 - __bfloat162float(h01.x));
                l01.y = __float2bfloat16(v1 - __bfloat162float(h01.y));
                h23.x = __float2bfloat16(v2); h23.y = __float2bfloat16(v3);
                l23.x = __float2bfloat16(v2 - __bfloat162float(h23.x));
                l23.y = __float2bfloat16(v3 - __bfloat162float(h23.y));
                uint32_t o0 = blk_off(r0,     col);
                uint32_t o1 = blk_off(r0 + 8, col);
                *reinterpret_cast<__nv_bfloat162*>(oh + o0) = h01;
                *reinterpret_cast<__nv_bfloat162*>(ol + o0) = l01;
                *reinterpret_cast<__nv_bfloat162*>(oh + o1) = h23;
                *reinterpret_cast<__nv_bfloat162*>(ol + o1) = l23;
            }
        }
        __threadfence();                 // release this CTA's u stores
        __syncthreads();                 // all threads fenced
        if (tid == 0) atomicAdd(&uflag[atile], 1u);
    }
}

// ---------------- launcher ----------------
extern "C" void kernel_launch(void* const* d_in, const int* in_sizes, int n_in,
                              void* d_out, int out_size)
{
    const float* x  = (const float*)d_in[0];
    const float* Wq = (const float*)d_in[1];
    const float* bq = (const float*)d_in[2];
    const float* Wk = (const float*)d_in[3];
    float* out = (float*)d_out;

    __nv_bfloat16 *xhi, *xlo, *m2hi, *m2lo, *uhi, *ulo;
    float *v2p, *rkp, *pptr;
    unsigned int *uflagp, *rcntp, *scntp, *srdp;
    cudaGetSymbolAddress((void**)&xhi,  g_xhi);
    cudaGetSymbolAddress((void**)&xlo,  g_xlo);
    cudaGetSymbolAddress((void**)&m2hi, g_m2hi);
    cudaGetSymbolAddress((void**)&m2lo, g_m2lo);
    cudaGetSymbolAddress((void**)&uhi,  g_uhi);
    cudaGetSymbolAddress((void**)&ulo,  g_ulo);
    cudaGetSymbolAddress((void**)&v2p,  g_v2);
    cudaGetSymbolAddress((void**)&rkp,  g_rk);
    cudaGetSymbolAddress((void**)&pptr, g_psum);
    cudaGetSymbolAddress((void**)&uflagp, g_uflag);
    cudaGetSymbolAddress((void**)&rcntp,  g_rcnt);
    cudaGetSymbolAddress((void**)&scntp,  g_scnt);
    cudaGetSymbolAddress((void**)&srdp,   g_srd);

    cudaFuncSetAttribute(fused_gemm_kernel, cudaFuncAttributeMaxDynamicSharedMemorySize, SMEM_DYN);

    // 1) preps (write blocked/swizzled layouts)
    v2_kernel<<<D_/8, 256>>>(Wk, bq, v2p);
    split_x_rk_kernel<<<B_*S_/4, 256>>>(x, v2p, xhi, xlo, rkp);
    dim3 mg(D_/32, D_/32);
    m2t_kernel<<<mg, 256>>>(Wk, Wq, m2hi, m2lo);

    // 2) fused proj + scores + softmax normalize (single output write)
    fused_gemm_kernel<<<N_PROJ_CTAS + S_/BN * S_/BM * B_, 256, SMEM_DYN>>>(
        xhi, xlo, m2hi, m2lo, uhi, ulo, rkp, out, pptr,
        uflagp, rcntp, scntp, srdp);
}